// round 14
// baseline (speedup 1.0000x reference)
#include <cuda_runtime.h>
#include <cuda_bf16.h>
#include <cstdint>
#include <math.h>

// Problem constants (fixed by the dataset)
#define NA      50000
#define NP      10000
#define NE      400000
#define IN_DIM  512
#define FEAT    128
#define NH      8
#define OD      32
#define HD      256   // NH*OD

// ---------------- scratch (static device globals; no allocation) -----------
__device__ float g_z[(size_t)NA * HD];        // 51.2 MB
__device__ float g_ssrc[(size_t)NA * NH];
__device__ float g_eval[(size_t)NE * NH];     // final leaky-relu logits
__device__ float g_alpha[(size_t)NE * NH];    // softmax weights, SORTED layout
__device__ float g_vfeat[NH * FEAT];
__device__ float g_uvec[NH * IN_DIM];
__device__ int   g_counts[NP];
__device__ int   g_offsets[NP];
__device__ int   g_cursor[NP];
__device__ int   g_edge_sorted[NE];
__device__ int   g_src_sorted[NE];

// ---------------- small utility kernels ------------------------------------
__global__ void k_zero_counts() {
    int t = blockIdx.x * blockDim.x + threadIdx.x;
    if (t < NP) g_counts[t] = 0;
}

__global__ void k_vfeat(const float* __restrict__ W_feat,
                        const float* __restrict__ W_attn) {
    int t = blockIdx.x * blockDim.x + threadIdx.x;
    if (t >= NH * FEAT) return;
    int h = t / FEAT, f = t % FEAT;
    float acc = 0.f;
#pragma unroll
    for (int d = 0; d < OD; ++d)
        acc += W_attn[2 * OD + d] * W_feat[(size_t)(h * OD + d) * FEAT + f];
    g_vfeat[t] = acc;
}

__global__ void k_uvec(const float* __restrict__ W_fc,
                       const float* __restrict__ W_attn) {
    int t = blockIdx.x * blockDim.x + threadIdx.x;
    if (t >= NH * IN_DIM) return;
    int h8 = t >> 9, k = t & (IN_DIM - 1);
    float acc = 0.f;
#pragma unroll
    for (int d = 0; d < OD; ++d)
        acc += W_attn[d] * W_fc[(size_t)(h8 * OD + d) * IN_DIM + k];
    g_uvec[t] = acc;
}

// ---------------- s_src[n,h] = h[n,:] . u[h,:]  (warp per node) -------------
__global__ void __launch_bounds__(256) k_ssrc2(const float* __restrict__ hmat) {
    __shared__ float su[NH * IN_DIM];   // 16 KB
    int tid = threadIdx.x;
    for (int i = tid; i < NH * IN_DIM; i += 256) su[i] = g_uvec[i];
    __syncthreads();

    int gw = (blockIdx.x * 256 + tid) >> 5;
    int lane = tid & 31;
    if (gw >= NA) return;
    const float4* hr = (const float4*)(hmat + (size_t)gw * IN_DIM);
    float acc[NH];
#pragma unroll
    for (int h8 = 0; h8 < NH; ++h8) acc[h8] = 0.f;
#pragma unroll
    for (int j = 0; j < 4; ++j) {
        float4 hv = hr[j * 32 + lane];
        int c = (j * 32 + lane) * 4;
#pragma unroll
        for (int h8 = 0; h8 < NH; ++h8) {
            const float* up = su + h8 * IN_DIM + c;
            acc[h8] += hv.x * up[0] + hv.y * up[1] + hv.z * up[2] + hv.w * up[3];
        }
    }
#pragma unroll
    for (int off = 16; off >= 1; off >>= 1)
#pragma unroll
        for (int h8 = 0; h8 < NH; ++h8)
            acc[h8] += __shfl_xor_sync(0xffffffffu, acc[h8], off);
    if (lane == 0) {
#pragma unroll
        for (int h8 = 0; h8 < NH; ++h8)
            g_ssrc[(size_t)gw * NH + h8] = acc[h8];
    }
}

// ============ 3-term compensated bf16 tensor-core GEMM (N-half) =============
#define GBM 128
#define GBN 128
#define GBK 16
#define KP  (GBK / 2)
#define SPAD 4
#define SSTR (KP + SPAD)
#define SIDX(buf, row, kp) ((((buf) * GBM) + (row)) * SSTR + (kp))
#define GEMM_SMEM_BYTES (4 * 2 * GBM * SSTR * 4)   // 49152

__device__ __forceinline__ void bf16_split2(float x, float y,
                                            uint32_t& hi, uint32_t& lo) {
    __nv_bfloat16 hx = __float2bfloat16_rn(x);
    __nv_bfloat16 hy = __float2bfloat16_rn(y);
    float rx = x - __bfloat162float(hx);
    float ry = y - __bfloat162float(hy);
    __nv_bfloat162 hp = __halves2bfloat162(hx, hy);
    __nv_bfloat162 lp = __floats2bfloat162_rn(rx, ry);
    hi = *reinterpret_cast<uint32_t*>(&hp);
    lo = *reinterpret_cast<uint32_t*>(&lp);
}

#define MMA_BF16(D, A0, A1, A2, A3, B0, B1)                                   \
    asm volatile(                                                             \
        "mma.sync.aligned.m16n8k16.row.col.f32.bf16.bf16.f32 "                \
        "{%0,%1,%2,%3}, {%4,%5,%6,%7}, {%8,%9}, {%0,%1,%2,%3};"               \
        : "+f"(D[0]), "+f"(D[1]), "+f"(D[2]), "+f"(D[3])                      \
        : "r"(A0), "r"(A1), "r"(A2), "r"(A3), "r"(B0), "r"(B1))

__global__ void __launch_bounds__(256, 2)
k_gemm_bf16x2(const float* __restrict__ A, const float* __restrict__ B,
              float* __restrict__ C, int bn) {
    const int M = NA, K = IN_DIM;
    extern __shared__ uint32_t sm[];
    uint32_t* Ah = sm;
    uint32_t* Al = sm + 2 * GBM * SSTR;
    uint32_t* Bh = sm + 4 * GBM * SSTR;
    uint32_t* Bl = sm + 6 * GBM * SSTR;

    const int bm = blockIdx.x * GBM;
    const int tid = threadIdx.x;
    const int warp = tid >> 5, lane = tid & 31;
    const int g = lane >> 2, tg = lane & 3;
    const int wm = (warp >> 2) * 64;
    const int wn = (warp & 3) * 32;

    float acc[4][4][4];
#pragma unroll
    for (int mi = 0; mi < 4; ++mi)
#pragma unroll
        for (int nj = 0; nj < 4; ++nj)
#pragma unroll
            for (int r = 0; r < 4; ++r) acc[mi][nj][r] = 0.f;

    const int lr = tid >> 2;
    const int lc = (tid & 3) * 4;
    const int lkp = (tid & 3) * 2;
    const int NITER = K / GBK;

    float4 ra[2], rb[2];
#pragma unroll
    for (int it = 0; it < 2; ++it) {
        int row = lr + it * 64;
        int grow = bm + row;
        ra[it] = (grow < M) ? *(const float4*)(A + (size_t)grow * K + lc)
                            : make_float4(0.f, 0.f, 0.f, 0.f);
        rb[it] = *(const float4*)(B + (size_t)(bn + row) * K + lc);
    }
#pragma unroll
    for (int it = 0; it < 2; ++it) {
        int row = lr + it * 64;
        uint32_t h0, l0, h1, l1;
        bf16_split2(ra[it].x, ra[it].y, h0, l0);
        bf16_split2(ra[it].z, ra[it].w, h1, l1);
        Ah[SIDX(0, row, lkp)] = h0; Ah[SIDX(0, row, lkp + 1)] = h1;
        Al[SIDX(0, row, lkp)] = l0; Al[SIDX(0, row, lkp + 1)] = l1;
        bf16_split2(rb[it].x, rb[it].y, h0, l0);
        bf16_split2(rb[it].z, rb[it].w, h1, l1);
        Bh[SIDX(0, row, lkp)] = h0; Bh[SIDX(0, row, lkp + 1)] = h1;
        Bl[SIDX(0, row, lkp)] = l0; Bl[SIDX(0, row, lkp + 1)] = l1;
    }
    __syncthreads();

    for (int t = 0; t < NITER; ++t) {
        if (t + 1 < NITER) {
            int kb = (t + 1) * GBK;
#pragma unroll
            for (int it = 0; it < 2; ++it) {
                int row = lr + it * 64;
                int grow = bm + row;
                ra[it] = (grow < M)
                    ? *(const float4*)(A + (size_t)grow * K + kb + lc)
                    : make_float4(0.f, 0.f, 0.f, 0.f);
                rb[it] = *(const float4*)(B + (size_t)(bn + row) * K + kb + lc);
            }
        }

        const int buf = t & 1;
        uint32_t bhf[4][2], blf[4][2];
#pragma unroll
        for (int nj = 0; nj < 4; ++nj) {
            int row = wn + nj * 8 + g;
            bhf[nj][0] = Bh[SIDX(buf, row, tg)];
            bhf[nj][1] = Bh[SIDX(buf, row, tg + 4)];
            blf[nj][0] = Bl[SIDX(buf, row, tg)];
            blf[nj][1] = Bl[SIDX(buf, row, tg + 4)];
        }
#pragma unroll
        for (int mi = 0; mi < 4; ++mi) {
            int r0 = wm + mi * 16 + g;
            uint32_t ah0 = Ah[SIDX(buf, r0, tg)];
            uint32_t ah1 = Ah[SIDX(buf, r0 + 8, tg)];
            uint32_t ah2 = Ah[SIDX(buf, r0, tg + 4)];
            uint32_t ah3 = Ah[SIDX(buf, r0 + 8, tg + 4)];
            uint32_t al0 = Al[SIDX(buf, r0, tg)];
            uint32_t al1 = Al[SIDX(buf, r0 + 8, tg)];
            uint32_t al2 = Al[SIDX(buf, r0, tg + 4)];
            uint32_t al3 = Al[SIDX(buf, r0 + 8, tg + 4)];
#pragma unroll
            for (int nj = 0; nj < 4; ++nj) {
                MMA_BF16(acc[mi][nj], al0, al1, al2, al3, bhf[nj][0], bhf[nj][1]);
                MMA_BF16(acc[mi][nj], ah0, ah1, ah2, ah3, blf[nj][0], blf[nj][1]);
                MMA_BF16(acc[mi][nj], ah0, ah1, ah2, ah3, bhf[nj][0], bhf[nj][1]);
            }
        }

        if (t + 1 < NITER) {
            const int nb = (t + 1) & 1;
#pragma unroll
            for (int it = 0; it < 2; ++it) {
                int row = lr + it * 64;
                uint32_t h0, l0, h1, l1;
                bf16_split2(ra[it].x, ra[it].y, h0, l0);
                bf16_split2(ra[it].z, ra[it].w, h1, l1);
                Ah[SIDX(nb, row, lkp)] = h0; Ah[SIDX(nb, row, lkp + 1)] = h1;
                Al[SIDX(nb, row, lkp)] = l0; Al[SIDX(nb, row, lkp + 1)] = l1;
                bf16_split2(rb[it].x, rb[it].y, h0, l0);
                bf16_split2(rb[it].z, rb[it].w, h1, l1);
                Bh[SIDX(nb, row, lkp)] = h0; Bh[SIDX(nb, row, lkp + 1)] = h1;
                Bl[SIDX(nb, row, lkp)] = l0; Bl[SIDX(nb, row, lkp + 1)] = l1;
            }
            __syncthreads();
        }
    }

#pragma unroll
    for (int mi = 0; mi < 4; ++mi) {
        int row0 = bm + wm + mi * 16 + g;
#pragma unroll
        for (int nj = 0; nj < 4; ++nj) {
            int col = bn + wn + nj * 8 + tg * 2;
            if (row0 < M)
                *(float2*)&C[(size_t)row0 * HD + col] =
                    make_float2(acc[mi][nj][0], acc[mi][nj][1]);
            if (row0 + 8 < M)
                *(float2*)&C[(size_t)(row0 + 8) * HD + col] =
                    make_float2(acc[mi][nj][2], acc[mi][nj][3]);
        }
    }
}

// ------ fused edge logits: eval = leaky(ssrc[src] + srl_emb . v^T) ----------
// Each thread owns sl-slice of FOUR edges: sv chunk loaded once per i and
// reused 4x (shared traffic per edge cut 4x vs one-edge-per-thread).
// warp = 16 edges (4 groups x 4 edges); block 256 = 128 edges; grid 3125.
__global__ void __launch_bounds__(256) k_sfeat(const float* __restrict__ srl,
                                               const int* __restrict__ src) {
    __shared__ float sv[NH][FEAT];
    int tid = threadIdx.x;
#pragma unroll
    for (int i = tid; i < NH * FEAT; i += 256)
        ((float*)sv)[i] = g_vfeat[i];
    __syncthreads();

    int warp = tid >> 5, lane = tid & 31;
    int grp = lane >> 3, sl = lane & 7;
    int e0 = blockIdx.x * 128 + warp * 16 + grp * 4;   // 4 consecutive edges

    const float4* rows[4];
#pragma unroll
    for (int j = 0; j < 4; ++j)
        rows[j] = (const float4*)(srl + (size_t)(e0 + j) * FEAT);

    float acc[4][NH];
#pragma unroll
    for (int j = 0; j < 4; ++j)
#pragma unroll
        for (int h = 0; h < NH; ++h) acc[j][h] = 0.f;

#pragma unroll
    for (int i = 0; i < 4; ++i) {
        int fb = (i * 8 + sl) * 4;
        float4 sc[NH];
#pragma unroll
        for (int h = 0; h < NH; ++h) sc[h] = *(const float4*)&sv[h][fb];
#pragma unroll
        for (int j = 0; j < 4; ++j) {
            float4 v = rows[j][i * 8 + sl];
#pragma unroll
            for (int h = 0; h < NH; ++h)
                acc[j][h] += v.x * sc[h].x + v.y * sc[h].y +
                             v.z * sc[h].z + v.w * sc[h].w;
        }
    }

#pragma unroll
    for (int j = 0; j < 4; ++j) {
        float ev = 0.f;
#pragma unroll
        for (int h = 0; h < NH; ++h) {
            float v = acc[j][h];
            v += __shfl_xor_sync(0xffffffffu, v, 1, 8);
            v += __shfl_xor_sync(0xffffffffu, v, 2, 8);
            v += __shfl_xor_sync(0xffffffffu, v, 4, 8);
            if (h == sl) ev = v;
        }
        int e = e0 + j;
        int sid = __ldg(&src[e]);
        float x = g_ssrc[(size_t)sid * NH + sl] + ev;
        g_eval[(size_t)e * NH + sl] = (x > 0.f) ? x : 0.01f * x;
    }
}

// ---------------- counting sort of edges by dst ----------------------------
__global__ void k_hist(const int* __restrict__ dst) {
    int t = blockIdx.x * blockDim.x + threadIdx.x;
    if (t < NE) atomicAdd(&g_counts[dst[t]], 1);
}

__global__ void __launch_bounds__(1024) k_scan() {
    __shared__ int sh[1024];
    int t = threadIdx.x;
    int base = t * 10;
    int local[10];
    int s = 0;
#pragma unroll
    for (int i = 0; i < 10; ++i) {
        int idx = base + i;
        int c = (idx < NP) ? g_counts[idx] : 0;
        local[i] = s;
        s += c;
    }
    sh[t] = s;
    __syncthreads();
    for (int off = 1; off < 1024; off <<= 1) {
        int v = (t >= off) ? sh[t - off] : 0;
        __syncthreads();
        sh[t] += v;
        __syncthreads();
    }
    int excl = sh[t] - s;
#pragma unroll
    for (int i = 0; i < 10; ++i) {
        int idx = base + i;
        if (idx < NP) {
            int o = excl + local[i];
            g_offsets[idx] = o;
            g_cursor[idx] = o;
        }
    }
}

__global__ void k_scatter(const int* __restrict__ dst,
                          const int* __restrict__ src) {
    int t = blockIdx.x * blockDim.x + threadIdx.x;
    if (t < NE) {
        int p = atomicAdd(&g_cursor[dst[t]], 1);
        g_edge_sorted[p] = t;
        g_src_sorted[p] = src[t];
    }
}

// -------- softmax weights per segment (off critical path) ------------------
__global__ void __launch_bounds__(256) k_alpha() {
    int p = blockIdx.x;
    int t = threadIdx.x;
    int h = t >> 5, lane = t & 31;
    int start = g_offsets[p];
    int cnt = g_counts[p];
    if (cnt == 0) return;

    float m = -3.0e38f;
    for (int i = lane; i < cnt; i += 32) {
        int eid = g_edge_sorted[start + i];
        m = fmaxf(m, g_eval[(size_t)eid * NH + h]);
    }
#pragma unroll
    for (int off = 16; off >= 1; off >>= 1)
        m = fmaxf(m, __shfl_xor_sync(0xffffffffu, m, off));

    float s = 0.f;
    for (int i = lane; i < cnt; i += 32) {
        int eid = g_edge_sorted[start + i];
        s += __expf(g_eval[(size_t)eid * NH + h] - m);
    }
#pragma unroll
    for (int off = 16; off >= 1; off >>= 1)
        s += __shfl_xor_sync(0xffffffffu, s, off);
    float inv = 1.f / s;

    for (int i = lane; i < cnt; i += 32) {
        int pos = start + i;
        int eid = g_edge_sorted[pos];
        g_alpha[(size_t)pos * NH + h] =
            __expf(g_eval[(size_t)eid * NH + h] - m) * inv;
    }
}

// -------- pure weighted gather over 128 output channels --------------------
__global__ void __launch_bounds__(128) k_gather(float* __restrict__ out,
                                                int colbase) {
    int p = blockIdx.x;
    int t = threadIdx.x;
    int ch = colbase + t;
    int start = g_offsets[p];
    int cnt = g_counts[p];
    int hh = ch >> 5;
    float acc = 0.f;
#pragma unroll 4
    for (int i = 0; i < cnt; ++i) {
        int pos = start + i;
        float a = __ldg(&g_alpha[(size_t)pos * NH + hh]);
        int sid = __ldg(&g_src_sorted[pos]);
        acc += a * __ldg(&g_z[(size_t)sid * HD + ch]);
    }
    out[(size_t)p * HD + ch] = acc;
}

// ---------------- launcher --------------------------------------------------
extern "C" void kernel_launch(void* const* d_in, const int* in_sizes, int n_in,
                              void* d_out, int out_size) {
    const float* h      = (const float*)d_in[0];
    const float* srl    = (const float*)d_in[1];
    const int*   src    = (const int*)d_in[2];
    const int*   dst    = (const int*)d_in[3];
    const float* W_fc   = (const float*)d_in[4];
    const float* W_feat = (const float*)d_in[5];
    const float* W_attn = (const float*)d_in[6];
    float* out = (float*)d_out;

    static cudaStream_t s1 = nullptr, s2 = nullptr, sg = nullptr;
    static cudaEvent_t ef = nullptr, ej2 = nullptr, ejA = nullptr,
                       eg0 = nullptr, eg1 = nullptr, ejg = nullptr;
    if (s1 == nullptr) {
        int lo, hi;
        cudaDeviceGetStreamPriorityRange(&lo, &hi);
        cudaStreamCreateWithPriority(&sg, cudaStreamNonBlocking, hi);
        cudaStreamCreateWithPriority(&s1, cudaStreamNonBlocking, lo);
        cudaStreamCreateWithPriority(&s2, cudaStreamNonBlocking, lo);
        cudaEventCreateWithFlags(&ef,  cudaEventDisableTiming);
        cudaEventCreateWithFlags(&ej2, cudaEventDisableTiming);
        cudaEventCreateWithFlags(&ejA, cudaEventDisableTiming);
        cudaEventCreateWithFlags(&eg0, cudaEventDisableTiming);
        cudaEventCreateWithFlags(&eg1, cudaEventDisableTiming);
        cudaEventCreateWithFlags(&ejg, cudaEventDisableTiming);
    }

    float* zptr;
    cudaGetSymbolAddress((void**)&zptr, g_z);

    // fork
    cudaEventRecord(ef, 0);
    cudaStreamWaitEvent(sg, ef, 0);
    cudaStreamWaitEvent(s1, ef, 0);
    cudaStreamWaitEvent(s2, ef, 0);

    // high-priority stream: GEMM halves (critical path)
    {
        int grid = (NA + GBM - 1) / GBM;   // 391
        k_gemm_bf16x2<<<grid, 256, GEMM_SMEM_BYTES, sg>>>(h, W_fc, zptr, 0);
        cudaEventRecord(eg0, sg);
        k_gemm_bf16x2<<<grid, 256, GEMM_SMEM_BYTES, sg>>>(h, W_fc, zptr, 128);
        cudaEventRecord(eg1, sg);
    }

    // side chain 2: attention logits (independent of GEMM)
    k_uvec<<<(NH * IN_DIM + 255) / 256, 256, 0, s2>>>(W_fc, W_attn);
    k_vfeat<<<(NH * FEAT + 255) / 256, 256, 0, s2>>>(W_feat, W_attn);
    k_ssrc2<<<(NA * 32 + 255) / 256, 256, 0, s2>>>(h);
    k_sfeat<<<NE / 128, 256, 0, s2>>>(srl, src);
    cudaEventRecord(ej2, s2);

    // side chain 1: counting sort, then alpha (needs logits too)
    k_zero_counts<<<(NP + 255) / 256, 256, 0, s1>>>();
    k_hist<<<(NE + 255) / 256, 256, 0, s1>>>(dst);
    k_scan<<<1, 1024, 0, s1>>>();
    k_scatter<<<(NE + 255) / 256, 256, 0, s1>>>(dst, src);
    cudaStreamWaitEvent(s1, ej2, 0);
    k_alpha<<<NP, 256, 0, s1>>>();
    cudaEventRecord(ejA, s1);

    // gather cols 0-127 overlaps GEMM half 2 (on s2)
    cudaStreamWaitEvent(s2, eg0, 0);
    cudaStreamWaitEvent(s2, ejA, 0);
    k_gather<<<NP, 128, 0, s2>>>(out, 0);
    cudaEventRecord(ejg, s2);

    // gather cols 128-255 after GEMM half 2 on stream 0, then join
    cudaStreamWaitEvent(0, eg1, 0);
    cudaStreamWaitEvent(0, ejA, 0);
    k_gather<<<NP, 128>>>(out, 128);
    cudaStreamWaitEvent(0, ejg, 0);
}

// round 15
// speedup vs baseline: 1.1104x; 1.1104x over previous
#include <cuda_runtime.h>
#include <cuda_bf16.h>
#include <cstdint>
#include <math.h>

// Problem constants (fixed by the dataset)
#define NA      50000
#define NP      10000
#define NE      400000
#define IN_DIM  512
#define FEAT    128
#define NH      8
#define OD      32
#define HD      256   // NH*OD

// ---------------- scratch (static device globals; no allocation) -----------
__device__ float g_z[(size_t)NA * HD];        // 51.2 MB
__device__ float g_ssrc[(size_t)NA * NH];
__device__ float g_eval[(size_t)NE * NH];     // final leaky-relu logits
__device__ float g_alpha[(size_t)NE * NH];    // softmax weights, SORTED layout
__device__ float g_vfeat[NH * FEAT];
__device__ float g_uvec[NH * IN_DIM];
__device__ int   g_counts[NP];
__device__ int   g_offsets[NP];
__device__ int   g_cursor[NP];
__device__ int   g_edge_sorted[NE];
__device__ int   g_src_sorted[NE];

// ---------------- small utility kernels ------------------------------------
__global__ void k_zero_counts() {
    int t = blockIdx.x * blockDim.x + threadIdx.x;
    if (t < NP) g_counts[t] = 0;
}

__global__ void k_vfeat(const float* __restrict__ W_feat,
                        const float* __restrict__ W_attn) {
    int t = blockIdx.x * blockDim.x + threadIdx.x;
    if (t >= NH * FEAT) return;
    int h = t / FEAT, f = t % FEAT;
    float acc = 0.f;
#pragma unroll
    for (int d = 0; d < OD; ++d)
        acc += W_attn[2 * OD + d] * W_feat[(size_t)(h * OD + d) * FEAT + f];
    g_vfeat[t] = acc;
}

__global__ void k_uvec(const float* __restrict__ W_fc,
                       const float* __restrict__ W_attn) {
    int t = blockIdx.x * blockDim.x + threadIdx.x;
    if (t >= NH * IN_DIM) return;
    int h8 = t >> 9, k = t & (IN_DIM - 1);
    float acc = 0.f;
#pragma unroll
    for (int d = 0; d < OD; ++d)
        acc += W_attn[d] * W_fc[(size_t)(h8 * OD + d) * IN_DIM + k];
    g_uvec[t] = acc;
}

// ---------------- s_src[n,h] = h[n,:] . u[h,:]  (warp per node) -------------
__global__ void __launch_bounds__(256) k_ssrc2(const float* __restrict__ hmat) {
    __shared__ float su[NH * IN_DIM];   // 16 KB
    int tid = threadIdx.x;
    for (int i = tid; i < NH * IN_DIM; i += 256) su[i] = g_uvec[i];
    __syncthreads();

    int gw = (blockIdx.x * 256 + tid) >> 5;
    int lane = tid & 31;
    if (gw >= NA) return;
    const float4* hr = (const float4*)(hmat + (size_t)gw * IN_DIM);
    float acc[NH];
#pragma unroll
    for (int h8 = 0; h8 < NH; ++h8) acc[h8] = 0.f;
#pragma unroll
    for (int j = 0; j < 4; ++j) {
        float4 hv = hr[j * 32 + lane];
        int c = (j * 32 + lane) * 4;
#pragma unroll
        for (int h8 = 0; h8 < NH; ++h8) {
            const float* up = su + h8 * IN_DIM + c;
            acc[h8] += hv.x * up[0] + hv.y * up[1] + hv.z * up[2] + hv.w * up[3];
        }
    }
#pragma unroll
    for (int off = 16; off >= 1; off >>= 1)
#pragma unroll
        for (int h8 = 0; h8 < NH; ++h8)
            acc[h8] += __shfl_xor_sync(0xffffffffu, acc[h8], off);
    if (lane == 0) {
#pragma unroll
        for (int h8 = 0; h8 < NH; ++h8)
            g_ssrc[(size_t)gw * NH + h8] = acc[h8];
    }
}

// ============ 3-term compensated bf16 tensor-core GEMM (N-half) =============
#define GBM 128
#define GBN 128
#define GBK 16
#define KP  (GBK / 2)
#define SPAD 4
#define SSTR (KP + SPAD)
#define SIDX(buf, row, kp) ((((buf) * GBM) + (row)) * SSTR + (kp))
#define GEMM_SMEM_BYTES (4 * 2 * GBM * SSTR * 4)   // 49152

__device__ __forceinline__ void bf16_split2(float x, float y,
                                            uint32_t& hi, uint32_t& lo) {
    __nv_bfloat16 hx = __float2bfloat16_rn(x);
    __nv_bfloat16 hy = __float2bfloat16_rn(y);
    float rx = x - __bfloat162float(hx);
    float ry = y - __bfloat162float(hy);
    __nv_bfloat162 hp = __halves2bfloat162(hx, hy);
    __nv_bfloat162 lp = __floats2bfloat162_rn(rx, ry);
    hi = *reinterpret_cast<uint32_t*>(&hp);
    lo = *reinterpret_cast<uint32_t*>(&lp);
}

#define MMA_BF16(D, A0, A1, A2, A3, B0, B1)                                   \
    asm volatile(                                                             \
        "mma.sync.aligned.m16n8k16.row.col.f32.bf16.bf16.f32 "                \
        "{%0,%1,%2,%3}, {%4,%5,%6,%7}, {%8,%9}, {%0,%1,%2,%3};"               \
        : "+f"(D[0]), "+f"(D[1]), "+f"(D[2]), "+f"(D[3])                      \
        : "r"(A0), "r"(A1), "r"(A2), "r"(A3), "r"(B0), "r"(B1))

__global__ void __launch_bounds__(256, 2)
k_gemm_bf16x2(const float* __restrict__ A, const float* __restrict__ B,
              float* __restrict__ C, int bn) {
    const int M = NA, K = IN_DIM;
    extern __shared__ uint32_t sm[];
    uint32_t* Ah = sm;
    uint32_t* Al = sm + 2 * GBM * SSTR;
    uint32_t* Bh = sm + 4 * GBM * SSTR;
    uint32_t* Bl = sm + 6 * GBM * SSTR;

    const int bm = blockIdx.x * GBM;
    const int tid = threadIdx.x;
    const int warp = tid >> 5, lane = tid & 31;
    const int g = lane >> 2, tg = lane & 3;
    const int wm = (warp >> 2) * 64;
    const int wn = (warp & 3) * 32;

    float acc[4][4][4];
#pragma unroll
    for (int mi = 0; mi < 4; ++mi)
#pragma unroll
        for (int nj = 0; nj < 4; ++nj)
#pragma unroll
            for (int r = 0; r < 4; ++r) acc[mi][nj][r] = 0.f;

    const int lr = tid >> 2;
    const int lc = (tid & 3) * 4;
    const int lkp = (tid & 3) * 2;
    const int NITER = K / GBK;

    float4 ra[2], rb[2];
#pragma unroll
    for (int it = 0; it < 2; ++it) {
        int row = lr + it * 64;
        int grow = bm + row;
        ra[it] = (grow < M) ? *(const float4*)(A + (size_t)grow * K + lc)
                            : make_float4(0.f, 0.f, 0.f, 0.f);
        rb[it] = *(const float4*)(B + (size_t)(bn + row) * K + lc);
    }
#pragma unroll
    for (int it = 0; it < 2; ++it) {
        int row = lr + it * 64;
        uint32_t h0, l0, h1, l1;
        bf16_split2(ra[it].x, ra[it].y, h0, l0);
        bf16_split2(ra[it].z, ra[it].w, h1, l1);
        Ah[SIDX(0, row, lkp)] = h0; Ah[SIDX(0, row, lkp + 1)] = h1;
        Al[SIDX(0, row, lkp)] = l0; Al[SIDX(0, row, lkp + 1)] = l1;
        bf16_split2(rb[it].x, rb[it].y, h0, l0);
        bf16_split2(rb[it].z, rb[it].w, h1, l1);
        Bh[SIDX(0, row, lkp)] = h0; Bh[SIDX(0, row, lkp + 1)] = h1;
        Bl[SIDX(0, row, lkp)] = l0; Bl[SIDX(0, row, lkp + 1)] = l1;
    }
    __syncthreads();

    for (int t = 0; t < NITER; ++t) {
        if (t + 1 < NITER) {
            int kb = (t + 1) * GBK;
#pragma unroll
            for (int it = 0; it < 2; ++it) {
                int row = lr + it * 64;
                int grow = bm + row;
                ra[it] = (grow < M)
                    ? *(const float4*)(A + (size_t)grow * K + kb + lc)
                    : make_float4(0.f, 0.f, 0.f, 0.f);
                rb[it] = *(const float4*)(B + (size_t)(bn + row) * K + kb + lc);
            }
        }

        const int buf = t & 1;
        uint32_t bhf[4][2], blf[4][2];
#pragma unroll
        for (int nj = 0; nj < 4; ++nj) {
            int row = wn + nj * 8 + g;
            bhf[nj][0] = Bh[SIDX(buf, row, tg)];
            bhf[nj][1] = Bh[SIDX(buf, row, tg + 4)];
            blf[nj][0] = Bl[SIDX(buf, row, tg)];
            blf[nj][1] = Bl[SIDX(buf, row, tg + 4)];
        }
#pragma unroll
        for (int mi = 0; mi < 4; ++mi) {
            int r0 = wm + mi * 16 + g;
            uint32_t ah0 = Ah[SIDX(buf, r0, tg)];
            uint32_t ah1 = Ah[SIDX(buf, r0 + 8, tg)];
            uint32_t ah2 = Ah[SIDX(buf, r0, tg + 4)];
            uint32_t ah3 = Ah[SIDX(buf, r0 + 8, tg + 4)];
            uint32_t al0 = Al[SIDX(buf, r0, tg)];
            uint32_t al1 = Al[SIDX(buf, r0 + 8, tg)];
            uint32_t al2 = Al[SIDX(buf, r0, tg + 4)];
            uint32_t al3 = Al[SIDX(buf, r0 + 8, tg + 4)];
#pragma unroll
            for (int nj = 0; nj < 4; ++nj) {
                MMA_BF16(acc[mi][nj], al0, al1, al2, al3, bhf[nj][0], bhf[nj][1]);
                MMA_BF16(acc[mi][nj], ah0, ah1, ah2, ah3, blf[nj][0], blf[nj][1]);
                MMA_BF16(acc[mi][nj], ah0, ah1, ah2, ah3, bhf[nj][0], bhf[nj][1]);
            }
        }

        if (t + 1 < NITER) {
            const int nb = (t + 1) & 1;
#pragma unroll
            for (int it = 0; it < 2; ++it) {
                int row = lr + it * 64;
                uint32_t h0, l0, h1, l1;
                bf16_split2(ra[it].x, ra[it].y, h0, l0);
                bf16_split2(ra[it].z, ra[it].w, h1, l1);
                Ah[SIDX(nb, row, lkp)] = h0; Ah[SIDX(nb, row, lkp + 1)] = h1;
                Al[SIDX(nb, row, lkp)] = l0; Al[SIDX(nb, row, lkp + 1)] = l1;
                bf16_split2(rb[it].x, rb[it].y, h0, l0);
                bf16_split2(rb[it].z, rb[it].w, h1, l1);
                Bh[SIDX(nb, row, lkp)] = h0; Bh[SIDX(nb, row, lkp + 1)] = h1;
                Bl[SIDX(nb, row, lkp)] = l0; Bl[SIDX(nb, row, lkp + 1)] = l1;
            }
            __syncthreads();
        }
    }

#pragma unroll
    for (int mi = 0; mi < 4; ++mi) {
        int row0 = bm + wm + mi * 16 + g;
#pragma unroll
        for (int nj = 0; nj < 4; ++nj) {
            int col = bn + wn + nj * 8 + tg * 2;
            if (row0 < M)
                *(float2*)&C[(size_t)row0 * HD + col] =
                    make_float2(acc[mi][nj][0], acc[mi][nj][1]);
            if (row0 + 8 < M)
                *(float2*)&C[(size_t)(row0 + 8) * HD + col] =
                    make_float2(acc[mi][nj][2], acc[mi][nj][3]);
        }
    }
}

// ------ fused edge logits: eval = leaky(ssrc[src] + srl_emb . v^T) ----------
// Each thread owns the sl-slice of TWO edges: sv chunk loaded once per
// i-step and reused for both edges (halves shared traffic per edge vs R12).
// warp = 8 edges (4 groups x 2); block 256 = 64 edges; grid 6250.
__global__ void __launch_bounds__(256) k_sfeat(const float* __restrict__ srl,
                                               const int* __restrict__ src) {
    __shared__ float sv[NH][FEAT];
    int tid = threadIdx.x;
#pragma unroll
    for (int i = tid; i < NH * FEAT; i += 256)
        ((float*)sv)[i] = g_vfeat[i];
    __syncthreads();

    int warp = tid >> 5, lane = tid & 31;
    int grp = lane >> 3, sl = lane & 7;
    int e0 = blockIdx.x * 64 + warp * 8 + grp * 2;   // 2 consecutive edges

    const float4* r0 = (const float4*)(srl + (size_t)e0 * FEAT);
    const float4* r1 = (const float4*)(srl + (size_t)(e0 + 1) * FEAT);

    float acc0[NH], acc1[NH];
#pragma unroll
    for (int h = 0; h < NH; ++h) { acc0[h] = 0.f; acc1[h] = 0.f; }

#pragma unroll
    for (int i = 0; i < 4; ++i) {
        int idx = i * 8 + sl;
        float4 v0 = r0[idx];
        float4 v1 = r1[idx];
        int fb = idx * 4;
#pragma unroll
        for (int h = 0; h < NH; ++h) {
            float4 s = *(const float4*)&sv[h][fb];
            acc0[h] += v0.x * s.x + v0.y * s.y + v0.z * s.z + v0.w * s.w;
            acc1[h] += v1.x * s.x + v1.y * s.y + v1.z * s.z + v1.w * s.w;
        }
    }

    float ev0 = 0.f, ev1 = 0.f;
#pragma unroll
    for (int h = 0; h < NH; ++h) {
        float v0 = acc0[h], v1 = acc1[h];
        v0 += __shfl_xor_sync(0xffffffffu, v0, 1, 8);
        v1 += __shfl_xor_sync(0xffffffffu, v1, 1, 8);
        v0 += __shfl_xor_sync(0xffffffffu, v0, 2, 8);
        v1 += __shfl_xor_sync(0xffffffffu, v1, 2, 8);
        v0 += __shfl_xor_sync(0xffffffffu, v0, 4, 8);
        v1 += __shfl_xor_sync(0xffffffffu, v1, 4, 8);
        if (h == sl) { ev0 = v0; ev1 = v1; }
    }
    int sid0 = __ldg(&src[e0]);
    int sid1 = __ldg(&src[e0 + 1]);
    float x0 = g_ssrc[(size_t)sid0 * NH + sl] + ev0;
    float x1 = g_ssrc[(size_t)sid1 * NH + sl] + ev1;
    g_eval[(size_t)e0 * NH + sl] = (x0 > 0.f) ? x0 : 0.01f * x0;
    g_eval[(size_t)(e0 + 1) * NH + sl] = (x1 > 0.f) ? x1 : 0.01f * x1;
}

// ---------------- counting sort of edges by dst ----------------------------
__global__ void k_hist(const int* __restrict__ dst) {
    int t = blockIdx.x * blockDim.x + threadIdx.x;
    if (t < NE) atomicAdd(&g_counts[dst[t]], 1);
}

__global__ void __launch_bounds__(1024) k_scan() {
    __shared__ int sh[1024];
    int t = threadIdx.x;
    int base = t * 10;
    int local[10];
    int s = 0;
#pragma unroll
    for (int i = 0; i < 10; ++i) {
        int idx = base + i;
        int c = (idx < NP) ? g_counts[idx] : 0;
        local[i] = s;
        s += c;
    }
    sh[t] = s;
    __syncthreads();
    for (int off = 1; off < 1024; off <<= 1) {
        int v = (t >= off) ? sh[t - off] : 0;
        __syncthreads();
        sh[t] += v;
        __syncthreads();
    }
    int excl = sh[t] - s;
#pragma unroll
    for (int i = 0; i < 10; ++i) {
        int idx = base + i;
        if (idx < NP) {
            int o = excl + local[i];
            g_offsets[idx] = o;
            g_cursor[idx] = o;
        }
    }
}

__global__ void k_scatter(const int* __restrict__ dst,
                          const int* __restrict__ src) {
    int t = blockIdx.x * blockDim.x + threadIdx.x;
    if (t < NE) {
        int p = atomicAdd(&g_cursor[dst[t]], 1);
        g_edge_sorted[p] = t;
        g_src_sorted[p] = src[t];
    }
}

// -------- softmax weights per segment (off critical path) ------------------
__global__ void __launch_bounds__(256) k_alpha() {
    int p = blockIdx.x;
    int t = threadIdx.x;
    int h = t >> 5, lane = t & 31;
    int start = g_offsets[p];
    int cnt = g_counts[p];
    if (cnt == 0) return;

    float m = -3.0e38f;
    for (int i = lane; i < cnt; i += 32) {
        int eid = g_edge_sorted[start + i];
        m = fmaxf(m, g_eval[(size_t)eid * NH + h]);
    }
#pragma unroll
    for (int off = 16; off >= 1; off >>= 1)
        m = fmaxf(m, __shfl_xor_sync(0xffffffffu, m, off));

    float s = 0.f;
    for (int i = lane; i < cnt; i += 32) {
        int eid = g_edge_sorted[start + i];
        s += __expf(g_eval[(size_t)eid * NH + h] - m);
    }
#pragma unroll
    for (int off = 16; off >= 1; off >>= 1)
        s += __shfl_xor_sync(0xffffffffu, s, off);
    float inv = 1.f / s;

    for (int i = lane; i < cnt; i += 32) {
        int pos = start + i;
        int eid = g_edge_sorted[pos];
        g_alpha[(size_t)pos * NH + h] =
            __expf(g_eval[(size_t)eid * NH + h] - m) * inv;
    }
}

// -------- pure weighted gather over 128 output channels --------------------
__global__ void __launch_bounds__(128) k_gather(float* __restrict__ out,
                                                int colbase) {
    int p = blockIdx.x;
    int t = threadIdx.x;
    int ch = colbase + t;
    int start = g_offsets[p];
    int cnt = g_counts[p];
    int hh = ch >> 5;
    float acc = 0.f;
#pragma unroll 4
    for (int i = 0; i < cnt; ++i) {
        int pos = start + i;
        float a = __ldg(&g_alpha[(size_t)pos * NH + hh]);
        int sid = __ldg(&g_src_sorted[pos]);
        acc += a * __ldg(&g_z[(size_t)sid * HD + ch]);
    }
    out[(size_t)p * HD + ch] = acc;
}

// ---------------- launcher --------------------------------------------------
extern "C" void kernel_launch(void* const* d_in, const int* in_sizes, int n_in,
                              void* d_out, int out_size) {
    const float* h      = (const float*)d_in[0];
    const float* srl    = (const float*)d_in[1];
    const int*   src    = (const int*)d_in[2];
    const int*   dst    = (const int*)d_in[3];
    const float* W_fc   = (const float*)d_in[4];
    const float* W_feat = (const float*)d_in[5];
    const float* W_attn = (const float*)d_in[6];
    float* out = (float*)d_out;

    static cudaStream_t s1 = nullptr, s2 = nullptr;
    static cudaEvent_t ef = nullptr, ej2 = nullptr, ejA = nullptr,
                       eg0 = nullptr, ejg = nullptr;
    if (s1 == nullptr) {
        cudaStreamCreateWithFlags(&s1, cudaStreamNonBlocking);
        cudaStreamCreateWithFlags(&s2, cudaStreamNonBlocking);
        cudaEventCreateWithFlags(&ef,  cudaEventDisableTiming);
        cudaEventCreateWithFlags(&ej2, cudaEventDisableTiming);
        cudaEventCreateWithFlags(&ejA, cudaEventDisableTiming);
        cudaEventCreateWithFlags(&eg0, cudaEventDisableTiming);
        cudaEventCreateWithFlags(&ejg, cudaEventDisableTiming);
    }

    float* zptr;
    cudaGetSymbolAddress((void**)&zptr, g_z);

    // fork
    cudaEventRecord(ef, 0);
    cudaStreamWaitEvent(s1, ef, 0);
    cudaStreamWaitEvent(s2, ef, 0);

    // side chain 2: attention logits (independent of GEMM; combine fused)
    k_uvec<<<(NH * IN_DIM + 255) / 256, 256, 0, s2>>>(W_fc, W_attn);
    k_vfeat<<<(NH * FEAT + 255) / 256, 256, 0, s2>>>(W_feat, W_attn);
    k_ssrc2<<<(NA * 32 + 255) / 256, 256, 0, s2>>>(h);
    k_sfeat<<<NE / 64, 256, 0, s2>>>(srl, src);
    cudaEventRecord(ej2, s2);

    // side chain 1: counting sort, then alpha (needs logits too)
    k_zero_counts<<<(NP + 255) / 256, 256, 0, s1>>>();
    k_hist<<<(NE + 255) / 256, 256, 0, s1>>>(dst);
    k_scan<<<1, 1024, 0, s1>>>();
    k_scatter<<<(NE + 255) / 256, 256, 0, s1>>>(dst, src);
    cudaStreamWaitEvent(s1, ej2, 0);
    k_alpha<<<NP, 256, 0, s1>>>();
    cudaEventRecord(ejA, s1);

    // main stream: GEMM halves (critical path)
    {
        int grid = (NA + GBM - 1) / GBM;   // 391
        k_gemm_bf16x2<<<grid, 256, GEMM_SMEM_BYTES>>>(h, W_fc, zptr, 0);
        cudaEventRecord(eg0, 0);
        k_gemm_bf16x2<<<grid, 256, GEMM_SMEM_BYTES>>>(h, W_fc, zptr, 128);
    }

    // gather cols 0-127 overlaps GEMM half 2 (on s2)
    cudaStreamWaitEvent(s2, eg0, 0);
    cudaStreamWaitEvent(s2, ejA, 0);
    k_gather<<<NP, 128, 0, s2>>>(out, 0);
    cudaEventRecord(ejg, s2);

    // gather cols 128-255 after GEMM half 2, then join
    cudaStreamWaitEvent(0, ejA, 0);
    k_gather<<<NP, 128>>>(out, 128);
    cudaStreamWaitEvent(0, ejg, 0);
}